// round 1
// baseline (speedup 1.0000x reference)
#include <cuda_runtime.h>

#define NN 50000
#define EE 600000
#define Hh 128
#define EDdim 16
#define Bb 256
#define Ll 5

// ---------------- device scratch (no allocs allowed) ----------------
__device__ float g_x[(size_t)NN * Hh];     // current node features (xn)
__device__ float g_h[(size_t)NN * Hh];     // h / mlp intermediate
__device__ float g_agg[(size_t)NN * Hh];   // aggregated messages
__device__ float g_eagg[(size_t)NN * EDdim]; // per-dst sum of edge_attr
__device__ int   g_deg[NN];
__device__ int   g_rowptr[NN + 1];
__device__ int   g_cursor[NN];
__device__ int   g_csr[EE];                // src ids grouped by dst
__device__ float g_counts[Bb];
__device__ float g_pooled[Bb * Hh];
__device__ float g_vn[Bb * Hh];

// ---------------- preprocessing kernels ----------------
__global__ void k_vn_init(const float* __restrict__ vninit) {
    g_vn[blockIdx.x * Hh + threadIdx.x] = vninit[threadIdx.x];
}

__global__ void k_counts(const int* __restrict__ batch) {
    int i = blockIdx.x * 256 + threadIdx.x;
    if (i < NN) atomicAdd(&g_counts[batch[i]], 1.0f);
}

__global__ void k_deg(const int* __restrict__ dst) {
    int e = blockIdx.x * 256 + threadIdx.x;
    if (e < EE) atomicAdd(&g_deg[dst[e]], 1);
}

// single-block exclusive scan of deg -> rowptr (+cursor copy)
__global__ void k_scan() {
    __shared__ int ss[1024];
    const int CH = (NN + 1023) / 1024;  // 49
    int t = threadIdx.x;
    int beg = t * CH;
    int end = min(beg + CH, NN);
    int s = 0;
    for (int i = beg; i < end; i++) s += g_deg[i];
    ss[t] = s;
    __syncthreads();
    for (int off = 1; off < 1024; off <<= 1) {
        int v = (t >= off) ? ss[t - off] : 0;
        __syncthreads();
        ss[t] += v;
        __syncthreads();
    }
    int run = (t == 0) ? 0 : ss[t - 1];
    for (int i = beg; i < end; i++) {
        g_rowptr[i] = run;
        g_cursor[i] = run;
        run += g_deg[i];
    }
    if (t == 1023) g_rowptr[NN] = ss[1023];
}

__global__ void k_fill(const int* __restrict__ src, const int* __restrict__ dst,
                       const float* __restrict__ eattr) {
    int e = blockIdx.x * 256 + threadIdx.x;
    if (e >= EE) return;
    int d = dst[e];
    int pos = atomicAdd(&g_cursor[d], 1);
    g_csr[pos] = src[e];
    const float* a = eattr + (size_t)e * EDdim;
#pragma unroll
    for (int k = 0; k < EDdim; k++) atomicAdd(&g_eagg[d * EDdim + k], a[k]);
}

// ---------------- tiled SGEMM: C[M,128] = A[M,128] @ W[128,128] (+epilogues) ----------------
// EPI 0: + bias + vn[batch[row]]         (node encode)
// EPI 1: relu(+bias)                     (mlp1)
// EPI 2: relu(+bias), atomic pooled add  (mlp2 -> xn, graph pooling)
template <int EPI>
__launch_bounds__(256, 3)
__global__ void gemm_bias(const float* __restrict__ A, const float* __restrict__ W,
                          const float* __restrict__ bias, float* __restrict__ C,
                          const int* __restrict__ batch, const float* __restrict__ vn,
                          float* __restrict__ pooled, int M) {
    __shared__ float As[16][64];
    __shared__ float Bs[16][128];
    const int tid = threadIdx.x;
    const int tx = tid & 15;        // col group  (x8)
    const int ty = tid >> 4;        // row group  (x4)
    const int brow = blockIdx.x * 64;

    const int arow = tid & 63;               // A smem row (conflict-free stores)
    const int akc  = (tid >> 6) << 2;        // 0,4,8,12
    const int grow = brow + arow;
    const int bro = tid >> 4;                // 0..15
    const int bco = (tid & 15) << 3;         // 0..120

    float acc[4][8];
#pragma unroll
    for (int i = 0; i < 4; i++)
#pragma unroll
        for (int j = 0; j < 8; j++) acc[i][j] = 0.f;

#pragma unroll 1
    for (int kt = 0; kt < 8; kt++) {
        float4 av = make_float4(0.f, 0.f, 0.f, 0.f);
        if (grow < M) av = *(const float4*)(A + (size_t)grow * Hh + kt * 16 + akc);
        const float* Wp = W + (size_t)(kt * 16 + bro) * Hh + bco;
        float4 b0 = *(const float4*)(Wp);
        float4 b1 = *(const float4*)(Wp + 4);
        __syncthreads();
        As[akc + 0][arow] = av.x;
        As[akc + 1][arow] = av.y;
        As[akc + 2][arow] = av.z;
        As[akc + 3][arow] = av.w;
        *(float4*)&Bs[bro][bco] = b0;
        *(float4*)&Bs[bro][bco + 4] = b1;
        __syncthreads();
#pragma unroll
        for (int k = 0; k < 16; k++) {
            float a[4], b[8];
            *(float4*)a = *(const float4*)&As[k][ty << 2];
            *(float4*)&b[0] = *(const float4*)&Bs[k][tx << 3];
            *(float4*)&b[4] = *(const float4*)&Bs[k][(tx << 3) + 4];
#pragma unroll
            for (int i = 0; i < 4; i++)
#pragma unroll
                for (int j = 0; j < 8; j++) acc[i][j] = fmaf(a[i], b[j], acc[i][j]);
        }
    }

    float bsv[8];
    *(float4*)&bsv[0] = *(const float4*)(bias + (tx << 3));
    *(float4*)&bsv[4] = *(const float4*)(bias + (tx << 3) + 4);
#pragma unroll
    for (int i = 0; i < 4; i++) {
        int row = brow + (ty << 2) + i;
        if (row >= M) continue;
        int g = 0;
        if (EPI == 0 || EPI == 2) g = batch[row];
        float o[8];
#pragma unroll
        for (int j = 0; j < 8; j++) {
            float v = acc[i][j] + bsv[j];
            if (EPI == 0) {
                v += vn[g * Hh + (tx << 3) + j];
            } else {
                v = fmaxf(v, 0.f);
            }
            o[j] = v;
            if (EPI == 2) atomicAdd(&pooled[g * Hh + (tx << 3) + j], v);
        }
        *(float4*)(C + (size_t)row * Hh + (tx << 3)) = *(float4*)&o[0];
        *(float4*)(C + (size_t)row * Hh + (tx << 3) + 4) = *(float4*)&o[4];
    }
}

// ---------------- SpMM: agg[v] = sum_{e in CSR(v)} h[src_e] + eagg[v]@eW + deg*eb ----------------
__launch_bounds__(256)
__global__ void spmm(const float* __restrict__ h, const float* __restrict__ eW,
                     const float* __restrict__ eb, float* __restrict__ agg) {
    __shared__ float sW[EDdim * Hh];
    for (int i = threadIdx.x; i < EDdim * Hh; i += 256) sW[i] = eW[i];
    __syncthreads();
    int warp = (blockIdx.x * 256 + threadIdx.x) >> 5;
    int lane = threadIdx.x & 31;
    if (warp >= NN) return;
    const int row = warp;
    const int c4 = lane << 2;

    float4 acc = make_float4(0.f, 0.f, 0.f, 0.f);
    const float* ea = g_eagg + row * EDdim;
#pragma unroll
    for (int k = 0; k < EDdim; k++) {
        float v = ea[k];
        float4 w = *(const float4*)&sW[k * Hh + c4];
        acc.x = fmaf(v, w.x, acc.x);
        acc.y = fmaf(v, w.y, acc.y);
        acc.z = fmaf(v, w.z, acc.z);
        acc.w = fmaf(v, w.w, acc.w);
    }
    int beg = g_rowptr[row];
    int end = g_rowptr[row + 1];
    float degf = (float)(end - beg);
    float4 bb = *(const float4*)(eb + c4);
    acc.x = fmaf(degf, bb.x, acc.x);
    acc.y = fmaf(degf, bb.y, acc.y);
    acc.z = fmaf(degf, bb.z, acc.z);
    acc.w = fmaf(degf, bb.w, acc.w);

    int e = beg;
    for (; e + 1 < end; e += 2) {
        int s0 = g_csr[e];
        int s1 = g_csr[e + 1];
        float4 h0 = *(const float4*)(h + (size_t)s0 * Hh + c4);
        float4 h1 = *(const float4*)(h + (size_t)s1 * Hh + c4);
        acc.x += h0.x + h1.x;
        acc.y += h0.y + h1.y;
        acc.z += h0.z + h1.z;
        acc.w += h0.w + h1.w;
    }
    if (e < end) {
        int s0 = g_csr[e];
        float4 h0 = *(const float4*)(h + (size_t)s0 * Hh + c4);
        acc.x += h0.x;
        acc.y += h0.y;
        acc.z += h0.z;
        acc.w += h0.w;
    }
    *(float4*)(agg + (size_t)row * Hh + c4) = acc;
}

// ---------------- virtual node update (tiny) ----------------
__global__ void vn_update(const float* __restrict__ w0, const float* __restrict__ b0,
                          const float* __restrict__ w1, const float* __restrict__ b1) {
    __shared__ float p[Hh];
    __shared__ float r0[Hh];
    int g = blockIdx.x, j = threadIdx.x;
    float cnt = fmaxf(g_counts[g], 1.f);
    p[j] = g_pooled[g * Hh + j] / cnt;
    __syncthreads();
    float s = b0[j];
    for (int k = 0; k < Hh; k++) s = fmaf(p[k], w0[k * Hh + j], s);
    r0[j] = fmaxf(s, 0.f);
    __syncthreads();
    float s2 = b1[j];
    for (int k = 0; k < Hh; k++) s2 = fmaf(r0[k], w1[k * Hh + j], s2);
    g_vn[g * Hh + j] += fmaxf(s2, 0.f);
}

// ---------------- final classifier ----------------
__global__ void final_fc(const float* __restrict__ fcW, const float* __restrict__ fcb,
                         float* __restrict__ out) {
    __shared__ float p[Hh];
    int g = blockIdx.x, j = threadIdx.x;
    float cnt = fmaxf(g_counts[g], 1.f);
    p[j] = g_pooled[g * Hh + j] / cnt;
    __syncthreads();
    float s = fcb[j];
    for (int k = 0; k < Hh; k++) s = fmaf(p[k], fcW[k * Hh + j], s);
    out[g * Hh + j] = s;
}

// ---------------- launch ----------------
extern "C" void kernel_launch(void* const* d_in, const int* in_sizes, int n_in,
                              void* d_out, int out_size) {
    const float* x      = (const float*)d_in[0];
    const float* eattr  = (const float*)d_in[1];
    const float* nodeW  = (const float*)d_in[2];
    const float* nodeB  = (const float*)d_in[3];
    const float* edgeW  = (const float*)d_in[4];
    const float* edgeB  = (const float*)d_in[5];
    const float* m1W    = (const float*)d_in[6];
    const float* m1B    = (const float*)d_in[7];
    const float* m2W    = (const float*)d_in[8];
    const float* m2B    = (const float*)d_in[9];
    const float* vnw0   = (const float*)d_in[10];
    const float* vnb0   = (const float*)d_in[11];
    const float* vnw1   = (const float*)d_in[12];
    const float* vnb1   = (const float*)d_in[13];
    const float* fcW    = (const float*)d_in[14];
    const float* fcB    = (const float*)d_in[15];
    const float* vninit = (const float*)d_in[16];
    const int*   eidx   = (const int*)d_in[17];
    const int*   batch  = (const int*)d_in[18];
    const int* srcp = eidx;
    const int* dstp = eidx + EE;
    float* out = (float*)d_out;

    void *p_eagg, *p_deg, *p_counts, *p_pooled, *p_x, *p_h, *p_agg, *p_vn;
    cudaGetSymbolAddress(&p_eagg, g_eagg);
    cudaGetSymbolAddress(&p_deg, g_deg);
    cudaGetSymbolAddress(&p_counts, g_counts);
    cudaGetSymbolAddress(&p_pooled, g_pooled);
    cudaGetSymbolAddress(&p_x, g_x);
    cudaGetSymbolAddress(&p_h, g_h);
    cudaGetSymbolAddress(&p_agg, g_agg);
    cudaGetSymbolAddress(&p_vn, g_vn);

    cudaMemsetAsync(p_eagg, 0, sizeof(float) * (size_t)NN * EDdim);
    cudaMemsetAsync(p_deg, 0, sizeof(int) * NN);
    cudaMemsetAsync(p_counts, 0, sizeof(float) * Bb);

    k_vn_init<<<Bb, Hh>>>(vninit);
    k_counts<<<(NN + 255) / 256, 256>>>(batch);
    k_deg<<<(EE + 255) / 256, 256>>>(dstp);
    k_scan<<<1, 1024>>>();
    k_fill<<<(EE + 255) / 256, 256>>>(srcp, dstp, eattr);

    const int GB = (NN + 63) / 64;     // 782 row tiles
    const int SPB = (NN + 7) / 8;      // one warp per node, 8 warps/block

    for (int l = 0; l < Ll; l++) {
        const float* Ain = (l == 0) ? x : (const float*)p_x;
        gemm_bias<0><<<GB, 256>>>(Ain, nodeW + (size_t)l * Hh * Hh, nodeB + l * Hh,
                                  (float*)p_h, batch, (const float*)p_vn, nullptr, NN);
        spmm<<<SPB, 256>>>((const float*)p_h, edgeW + (size_t)l * EDdim * Hh,
                           edgeB + l * Hh, (float*)p_agg);
        cudaMemsetAsync(p_pooled, 0, sizeof(float) * Bb * Hh);
        gemm_bias<1><<<GB, 256>>>((const float*)p_agg, m1W + (size_t)l * Hh * Hh,
                                  m1B + l * Hh, (float*)p_h, nullptr, nullptr, nullptr, NN);
        gemm_bias<2><<<GB, 256>>>((const float*)p_h, m2W + (size_t)l * Hh * Hh,
                                  m2B + l * Hh, (float*)p_x, batch, nullptr,
                                  (float*)p_pooled, NN);
        if (l < Ll - 1) vn_update<<<Bb, Hh>>>(vnw0, vnb0, vnw1, vnb1);
    }
    final_fc<<<Bb, Hh>>>(fcW, fcB, out);
}

// round 4
// speedup vs baseline: 2.4298x; 2.4298x over previous
#include <cuda_runtime.h>
#include <cuda_bf16.h>
#include <stdint.h>

#define NN 50000
#define EE 600000
#define Hh 128
#define EDdim 16
#define Bb 256
#define Ll 5
#define NBLK 196                    // ceil(NN/256)
#define GBLK ((NN + 127) / 128)     // 391 GEMM CTAs
#define STRIDE 136                  // padded bf16 row stride in smem

// ======================= device scratch =======================
__device__ float g_x[(size_t)NN * Hh];
__device__ float g_h[(size_t)NN * Hh];
__device__ float g_agg[(size_t)NN * Hh];
__device__ float g_eagg[(size_t)NN * EDdim];
__device__ int   g_deg[NN];
__device__ int   g_rowptr[NN + 1];
__device__ int   g_cursor[NN];
__device__ int   g_srcA[EE];
__device__ int   g_eidA[EE];
__device__ int   g_bsum[NBLK];
__device__ int   g_boff[NBLK];
__device__ float g_counts[Bb];
__device__ float g_pooled[Bb * Hh];
__device__ float g_vn[Bb * Hh];
__device__ __nv_bfloat16 g_whi[15 * Hh * Hh];  // [mat][n][k] transposed split
__device__ __nv_bfloat16 g_wlo[15 * Hh * Hh];

// ======================= preprocessing =======================
__global__ void k_wsplit(const float* __restrict__ nodeW, const float* __restrict__ m1W,
                         const float* __restrict__ m2W) {
    int b = blockIdx.x;
    int mat = b >> 6;
    int idx = ((b & 63) << 8) + threadIdx.x;   // 0..16383 over [n][k]
    const float* Wsrc = (mat < 5) ? (nodeW + (size_t)mat * Hh * Hh)
                      : (mat < 10) ? (m1W + (size_t)(mat - 5) * Hh * Hh)
                      : (m2W + (size_t)(mat - 10) * Hh * Hh);
    int n = idx >> 7, k = idx & 127;
    float w = Wsrc[k * Hh + n];
    __nv_bfloat16 hi = __float2bfloat16(w);
    __nv_bfloat16 lo = __float2bfloat16(w - __bfloat162float(hi));
    g_whi[(size_t)mat * Hh * Hh + idx] = hi;
    g_wlo[(size_t)mat * Hh * Hh + idx] = lo;
}

__global__ void k_vn_init(const float* __restrict__ vninit) {
    g_vn[blockIdx.x * Hh + threadIdx.x] = vninit[threadIdx.x];
}

__global__ void k_counts(const int* __restrict__ batch) {
    int i = blockIdx.x * 256 + threadIdx.x;
    if (i < NN) atomicAdd(&g_counts[batch[i]], 1.0f);
}

__global__ void k_deg(const int* __restrict__ dst) {
    int e = blockIdx.x * 256 + threadIdx.x;
    if (e < EE) atomicAdd(&g_deg[dst[e]], 1);
}

__global__ void k_bsum() {
    __shared__ int s[256];
    int t = threadIdx.x;
    int i = blockIdx.x * 256 + t;
    s[t] = (i < NN) ? g_deg[i] : 0;
    __syncthreads();
    for (int o = 128; o > 0; o >>= 1) {
        if (t < o) s[t] += s[t + o];
        __syncthreads();
    }
    if (t == 0) g_bsum[blockIdx.x] = s[0];
}

__global__ void k_bscan() {
    __shared__ int s[256];
    int t = threadIdx.x;
    int v = (t < NBLK) ? g_bsum[t] : 0;
    s[t] = v;
    __syncthreads();
    for (int o = 1; o < 256; o <<= 1) {
        int u = (t >= o) ? s[t - o] : 0;
        __syncthreads();
        s[t] += u;
        __syncthreads();
    }
    if (t < NBLK) g_boff[t] = s[t] - v;
    if (t == 255) g_rowptr[NN] = s[255];
}

__global__ void k_bfill() {
    __shared__ int s[256];
    int t = threadIdx.x;
    int i = blockIdx.x * 256 + t;
    int v = (i < NN) ? g_deg[i] : 0;
    s[t] = v;
    __syncthreads();
    for (int o = 1; o < 256; o <<= 1) {
        int u = (t >= o) ? s[t - o] : 0;
        __syncthreads();
        s[t] += u;
        __syncthreads();
    }
    if (i < NN) {
        int pos = g_boff[blockIdx.x] + s[t] - v;
        g_rowptr[i] = pos;
        g_cursor[i] = pos;
    }
}

__global__ void k_fill(const int* __restrict__ src, const int* __restrict__ dst) {
    int e = blockIdx.x * 256 + threadIdx.x;
    if (e >= EE) return;
    int d = dst[e];
    int pos = atomicAdd(&g_cursor[d], 1);
    g_srcA[pos] = src[e];
    g_eidA[pos] = e;
}

__global__ void k_eagg(const float* __restrict__ eattr) {
    int w = (blockIdx.x * 256 + threadIdx.x) >> 5;
    int lane = threadIdx.x & 31;
    if (w >= NN || lane >= EDdim) return;
    int beg = g_rowptr[w], end = g_rowptr[w + 1];
    float s = 0.f;
    for (int e = beg; e < end; e++) {
        int eid = g_eidA[e];
        s += eattr[(size_t)eid * EDdim + lane];
    }
    g_eagg[w * EDdim + lane] = s;
}

// ======================= HMMA (mma.sync) bf16-split GEMM =======================
// C[M,128] = A[M,128] @ W[128,128]; D = Ahi@Bhi + Ahi@Blo + Alo@Bhi (fp32 accum).
// EPI 0: +bias +vn[batch]; EPI 1: relu(+bias); EPI 2: relu(+bias) + pooled atomic.

__device__ __forceinline__ void mma16816(float* c, uint32_t a0, uint32_t a1, uint32_t a2,
                                         uint32_t a3, uint32_t b0, uint32_t b1) {
    asm volatile(
        "mma.sync.aligned.m16n8k16.row.col.f32.bf16.bf16.f32 "
        "{%0,%1,%2,%3}, {%4,%5,%6,%7}, {%8,%9}, {%0,%1,%2,%3};"
        : "+f"(c[0]), "+f"(c[1]), "+f"(c[2]), "+f"(c[3])
        : "r"(a0), "r"(a1), "r"(a2), "r"(a3), "r"(b0), "r"(b1));
}

__device__ __forceinline__ void split8(const float* a, uint4& h, uint4& l) {
    uint32_t hw[4], lw[4];
#pragma unroll
    for (int i = 0; i < 4; i++) {
        float x0 = a[2 * i], x1 = a[2 * i + 1];
        __nv_bfloat16 h0 = __float2bfloat16(x0);
        __nv_bfloat16 h1 = __float2bfloat16(x1);
        __nv_bfloat16 l0 = __float2bfloat16(x0 - __bfloat162float(h0));
        __nv_bfloat16 l1 = __float2bfloat16(x1 - __bfloat162float(h1));
        hw[i] = (uint32_t)__bfloat16_as_ushort(h0) | ((uint32_t)__bfloat16_as_ushort(h1) << 16);
        lw[i] = (uint32_t)__bfloat16_as_ushort(l0) | ((uint32_t)__bfloat16_as_ushort(l1) << 16);
    }
    h = make_uint4(hw[0], hw[1], hw[2], hw[3]);
    l = make_uint4(lw[0], lw[1], lw[2], lw[3]);
}

#define SM_AHI 0
#define SM_ALO (128 * STRIDE)
#define SM_BHI (2 * 128 * STRIDE)
#define SM_BLO (3 * 128 * STRIDE)
#define GEMM_SMEM (4 * 128 * STRIDE * 2)   // bytes (bf16 elems * 2)

template <int EPI>
__launch_bounds__(256, 1)
__global__ void gemm_tc(const float* __restrict__ A, const __nv_bfloat16* __restrict__ Whi,
                        const __nv_bfloat16* __restrict__ Wlo, const float* __restrict__ bias,
                        float* __restrict__ C, const int* __restrict__ batch,
                        const float* __restrict__ vn, float* __restrict__ pooled, int M) {
    extern __shared__ __nv_bfloat16 sm[];
    const int tid = threadIdx.x;
    const int wid = tid >> 5;
    const int lane = tid & 31;
    const int tb = blockIdx.x * 128;

    // ---- load + split A (128 rows x 128 fp32) ----
#pragma unroll
    for (int it = 0; it < 8; it++) {
        int idx = it * 256 + tid;          // 0..2047
        int row = idx >> 4;
        int c8 = (idx & 15) << 3;
        int grow = tb + row;
        float av[8] = {0, 0, 0, 0, 0, 0, 0, 0};
        if (grow < M) {
            *(float4*)&av[0] = *(const float4*)(A + (size_t)grow * Hh + c8);
            *(float4*)&av[4] = *(const float4*)(A + (size_t)grow * Hh + c8 + 4);
        }
        uint4 hv, lv;
        split8(av, hv, lv);
        *(uint4*)&sm[SM_AHI + row * STRIDE + c8] = hv;
        *(uint4*)&sm[SM_ALO + row * STRIDE + c8] = lv;
    }
    // ---- load pre-split W [n][k] ----
#pragma unroll
    for (int it = 0; it < 8; it++) {
        int idx = it * 256 + tid;
        int n = idx >> 4;
        int k8 = (idx & 15) << 3;
        uint4 hv = *(const uint4*)(Whi + (size_t)n * Hh + k8);
        uint4 lv = *(const uint4*)(Wlo + (size_t)n * Hh + k8);
        *(uint4*)&sm[SM_BHI + n * STRIDE + k8] = hv;
        *(uint4*)&sm[SM_BLO + n * STRIDE + k8] = lv;
    }
    __syncthreads();

    // ---- compute: warp owns rows [wid*16, wid*16+16), all 128 cols ----
    const int g = lane >> 2;
    const int tig = lane & 3;
    const int r0 = wid * 16 + g;          // local row for c0,c1
    const int r1 = r0 + 8;                // local row for c2,c3

    float c[16][4];
#pragma unroll
    for (int n = 0; n < 16; n++)
#pragma unroll
        for (int j = 0; j < 4; j++) c[n][j] = 0.f;

#pragma unroll 1
    for (int k = 0; k < 8; k++) {
        int k0 = k << 4;
        int ca = k0 + 2 * tig;
        uint32_t ah0 = *(const uint32_t*)&sm[SM_AHI + r0 * STRIDE + ca];
        uint32_t ah1 = *(const uint32_t*)&sm[SM_AHI + r1 * STRIDE + ca];
        uint32_t ah2 = *(const uint32_t*)&sm[SM_AHI + r0 * STRIDE + ca + 8];
        uint32_t ah3 = *(const uint32_t*)&sm[SM_AHI + r1 * STRIDE + ca + 8];
        uint32_t al0 = *(const uint32_t*)&sm[SM_ALO + r0 * STRIDE + ca];
        uint32_t al1 = *(const uint32_t*)&sm[SM_ALO + r1 * STRIDE + ca];
        uint32_t al2 = *(const uint32_t*)&sm[SM_ALO + r0 * STRIDE + ca + 8];
        uint32_t al3 = *(const uint32_t*)&sm[SM_ALO + r1 * STRIDE + ca + 8];
#pragma unroll
        for (int n = 0; n < 16; n++) {
            int brow = (n << 3) + g;
            uint32_t bh0 = *(const uint32_t*)&sm[SM_BHI + brow * STRIDE + ca];
            uint32_t bh1 = *(const uint32_t*)&sm[SM_BHI + brow * STRIDE + ca + 8];
            uint32_t bl0 = *(const uint32_t*)&sm[SM_BLO + brow * STRIDE + ca];
            uint32_t bl1 = *(const uint32_t*)&sm[SM_BLO + brow * STRIDE + ca + 8];
            mma16816(c[n], ah0, ah1, ah2, ah3, bh0, bh1);
            mma16816(c[n], ah0, ah1, ah2, ah3, bl0, bl1);
            mma16816(c[n], al0, al1, al2, al3, bh0, bh1);
        }
    }

    // ---- epilogue ----
    int gr0 = tb + r0;
    int gr1 = tb + r1;
    bool v0 = gr0 < M, v1 = gr1 < M;
    int gc0 = 0, gc1 = 0;
    if (EPI == 0 || EPI == 2) {
        if (v0) gc0 = batch[gr0];
        if (v1) gc1 = batch[gr1];
    }
#pragma unroll
    for (int n = 0; n < 16; n++) {
        int col = (n << 3) + 2 * tig;
        float2 bv = *(const float2*)(bias + col);
        float o0x = c[n][0] + bv.x, o0y = c[n][1] + bv.y;
        float o1x = c[n][2] + bv.x, o1y = c[n][3] + bv.y;
        if (EPI == 0) {
            if (v0) {
                float2 vv = *(const float2*)(vn + gc0 * Hh + col);
                o0x += vv.x; o0y += vv.y;
            }
            if (v1) {
                float2 vv = *(const float2*)(vn + gc1 * Hh + col);
                o1x += vv.x; o1y += vv.y;
            }
        } else {
            o0x = fmaxf(o0x, 0.f); o0y = fmaxf(o0y, 0.f);
            o1x = fmaxf(o1x, 0.f); o1y = fmaxf(o1y, 0.f);
        }
        if (v0) {
            *(float2*)(C + (size_t)gr0 * Hh + col) = make_float2(o0x, o0y);
            if (EPI == 2) {
                atomicAdd(&pooled[gc0 * Hh + col], o0x);
                atomicAdd(&pooled[gc0 * Hh + col + 1], o0y);
            }
        }
        if (v1) {
            *(float2*)(C + (size_t)gr1 * Hh + col) = make_float2(o1x, o1y);
            if (EPI == 2) {
                atomicAdd(&pooled[gc1 * Hh + col], o1x);
                atomicAdd(&pooled[gc1 * Hh + col + 1], o1y);
            }
        }
    }
}

// ======================= SpMM =======================
__launch_bounds__(256)
__global__ void spmm(const float* __restrict__ h, const float* __restrict__ eW,
                     const float* __restrict__ eb, float* __restrict__ agg) {
    __shared__ float sW[EDdim * Hh];
    for (int i = threadIdx.x; i < EDdim * Hh; i += 256) sW[i] = eW[i];
    __syncthreads();
    int warp = (blockIdx.x * 256 + threadIdx.x) >> 5;
    int lane = threadIdx.x & 31;
    if (warp >= NN) return;
    const int row = warp;
    const int c4 = lane << 2;

    float4 acc = make_float4(0.f, 0.f, 0.f, 0.f);
    const float* ea = g_eagg + row * EDdim;
#pragma unroll
    for (int k = 0; k < EDdim; k++) {
        float v = ea[k];
        float4 w = *(const float4*)&sW[k * Hh + c4];
        acc.x = fmaf(v, w.x, acc.x);
        acc.y = fmaf(v, w.y, acc.y);
        acc.z = fmaf(v, w.z, acc.z);
        acc.w = fmaf(v, w.w, acc.w);
    }
    int beg = g_rowptr[row];
    int end = g_rowptr[row + 1];
    float degf = (float)(end - beg);
    float4 bb = *(const float4*)(eb + c4);
    acc.x = fmaf(degf, bb.x, acc.x);
    acc.y = fmaf(degf, bb.y, acc.y);
    acc.z = fmaf(degf, bb.z, acc.z);
    acc.w = fmaf(degf, bb.w, acc.w);

    int e = beg;
    for (; e + 1 < end; e += 2) {
        int s0 = g_srcA[e];
        int s1 = g_srcA[e + 1];
        float4 h0 = *(const float4*)(h + (size_t)s0 * Hh + c4);
        float4 h1 = *(const float4*)(h + (size_t)s1 * Hh + c4);
        acc.x += h0.x + h1.x;
        acc.y += h0.y + h1.y;
        acc.z += h0.z + h1.z;
        acc.w += h0.w + h1.w;
    }
    if (e < end) {
        int s0 = g_srcA[e];
        float4 h0 = *(const float4*)(h + (size_t)s0 * Hh + c4);
        acc.x += h0.x;
        acc.y += h0.y;
        acc.z += h0.z;
        acc.w += h0.w;
    }
    *(float4*)(agg + (size_t)row * Hh + c4) = acc;
}

// ======================= small dense tails =======================
__global__ void vn_update(const float* __restrict__ w0, const float* __restrict__ b0,
                          const float* __restrict__ w1, const float* __restrict__ b1) {
    __shared__ float p[Hh];
    __shared__ float r0[Hh];
    int g = blockIdx.x, j = threadIdx.x;
    float cnt = fmaxf(g_counts[g], 1.f);
    p[j] = g_pooled[g * Hh + j] / cnt;
    __syncthreads();
    float s = b0[j];
    for (int k = 0; k < Hh; k++) s = fmaf(p[k], w0[k * Hh + j], s);
    r0[j] = fmaxf(s, 0.f);
    __syncthreads();
    float s2 = b1[j];
    for (int k = 0; k < Hh; k++) s2 = fmaf(r0[k], w1[k * Hh + j], s2);
    g_vn[g * Hh + j] += fmaxf(s2, 0.f);
}

__global__ void final_fc(const float* __restrict__ fcW, const float* __restrict__ fcb,
                         float* __restrict__ out) {
    __shared__ float p[Hh];
    int g = blockIdx.x, j = threadIdx.x;
    float cnt = fmaxf(g_counts[g], 1.f);
    p[j] = g_pooled[g * Hh + j] / cnt;
    __syncthreads();
    float s = fcb[j];
    for (int k = 0; k < Hh; k++) s = fmaf(p[k], fcW[k * Hh + j], s);
    out[g * Hh + j] = s;
}

// ======================= launch =======================
extern "C" void kernel_launch(void* const* d_in, const int* in_sizes, int n_in,
                              void* d_out, int out_size) {
    const float* x      = (const float*)d_in[0];
    const float* eattr  = (const float*)d_in[1];
    const float* nodeW  = (const float*)d_in[2];
    const float* nodeB  = (const float*)d_in[3];
    const float* edgeW  = (const float*)d_in[4];
    const float* edgeB  = (const float*)d_in[5];
    const float* m1W    = (const float*)d_in[6];
    const float* m1B    = (const float*)d_in[7];
    const float* m2W    = (const float*)d_in[8];
    const float* m2B    = (const float*)d_in[9];
    const float* vnw0   = (const float*)d_in[10];
    const float* vnb0   = (const float*)d_in[11];
    const float* vnw1   = (const float*)d_in[12];
    const float* vnb1   = (const float*)d_in[13];
    const float* fcW    = (const float*)d_in[14];
    const float* fcB    = (const float*)d_in[15];
    const float* vninit = (const float*)d_in[16];
    const int*   eidx   = (const int*)d_in[17];
    const int*   batch  = (const int*)d_in[18];
    const int* srcp = eidx;
    const int* dstp = eidx + EE;
    float* out = (float*)d_out;

    void *p_deg, *p_counts, *p_pooled, *p_x, *p_h, *p_agg, *p_vn, *p_whi, *p_wlo;
    cudaGetSymbolAddress(&p_deg, g_deg);
    cudaGetSymbolAddress(&p_counts, g_counts);
    cudaGetSymbolAddress(&p_pooled, g_pooled);
    cudaGetSymbolAddress(&p_x, g_x);
    cudaGetSymbolAddress(&p_h, g_h);
    cudaGetSymbolAddress(&p_agg, g_agg);
    cudaGetSymbolAddress(&p_vn, g_vn);
    cudaGetSymbolAddress(&p_whi, g_whi);
    cudaGetSymbolAddress(&p_wlo, g_wlo);

    cudaFuncSetAttribute(gemm_tc<0>, cudaFuncAttributeMaxDynamicSharedMemorySize, GEMM_SMEM);
    cudaFuncSetAttribute(gemm_tc<1>, cudaFuncAttributeMaxDynamicSharedMemorySize, GEMM_SMEM);
    cudaFuncSetAttribute(gemm_tc<2>, cudaFuncAttributeMaxDynamicSharedMemorySize, GEMM_SMEM);

    cudaMemsetAsync(p_deg, 0, sizeof(int) * NN);
    cudaMemsetAsync(p_counts, 0, sizeof(float) * Bb);

    k_wsplit<<<960, 256>>>(nodeW, m1W, m2W);
    k_vn_init<<<Bb, Hh>>>(vninit);
    k_counts<<<(NN + 255) / 256, 256>>>(batch);
    k_deg<<<(EE + 255) / 256, 256>>>(dstp);
    k_bsum<<<NBLK, 256>>>();
    k_bscan<<<1, 256>>>();
    k_bfill<<<NBLK, 256>>>();
    k_fill<<<(EE + 255) / 256, 256>>>(srcp, dstp);
    k_eagg<<<(NN + 7) / 8, 256>>>(eattr);

    const int SPB = (NN + 7) / 8;
    const __nv_bfloat16* whi = (const __nv_bfloat16*)p_whi;
    const __nv_bfloat16* wlo = (const __nv_bfloat16*)p_wlo;

    for (int l = 0; l < Ll; l++) {
        const float* Ain = (l == 0) ? x : (const float*)p_x;
        gemm_tc<0><<<GBLK, 256, GEMM_SMEM>>>(Ain, whi + (size_t)l * Hh * Hh,
                                             wlo + (size_t)l * Hh * Hh, nodeB + l * Hh,
                                             (float*)p_h, batch, (const float*)p_vn, nullptr, NN);
        spmm<<<SPB, 256>>>((const float*)p_h, edgeW + (size_t)l * EDdim * Hh,
                           edgeB + l * Hh, (float*)p_agg);
        cudaMemsetAsync(p_pooled, 0, sizeof(float) * Bb * Hh);
        gemm_tc<1><<<GBLK, 256, GEMM_SMEM>>>((const float*)p_agg, whi + (size_t)(5 + l) * Hh * Hh,
                                             wlo + (size_t)(5 + l) * Hh * Hh, m1B + l * Hh,
                                             (float*)p_h, nullptr, nullptr, nullptr, NN);
        gemm_tc<2><<<GBLK, 256, GEMM_SMEM>>>((const float*)p_h, whi + (size_t)(10 + l) * Hh * Hh,
                                             wlo + (size_t)(10 + l) * Hh * Hh, m2B + l * Hh,
                                             (float*)p_x, batch, nullptr, (float*)p_pooled, NN);
        if (l < Ll - 1) vn_update<<<Bb, Hh>>>(vnw0, vnb0, vnw1, vnb1);
    }
    final_fc<<<Bb, Hh>>>(fcW, fcB, out);
}

// round 5
// speedup vs baseline: 3.7438x; 1.5407x over previous
#include <cuda_runtime.h>
#include <cuda_bf16.h>
#include <stdint.h>

#define NN 50000
#define EE 600000
#define Hh 128
#define EDdim 16
#define Bb 256
#define Ll 5
#define NBLK 196                    // ceil(NN/256)
#define GBLK ((NN + 127) / 128)     // 391 GEMM CTAs
#define STRIDE 136                  // padded bf16 row stride in smem
#define BLO_ELEM (128 * STRIDE)     // lo-plane offset in bf16 elems
#define GEMM_SMEM (2 * 128 * STRIDE * 2)   // B hi+lo only: 69,632 bytes

// ======================= device scratch =======================
__device__ float g_x[(size_t)NN * Hh];
__device__ float g_h[(size_t)NN * Hh];
__device__ float g_agg[(size_t)NN * Hh];
__device__ float g_eagg[(size_t)NN * EDdim];
__device__ int   g_deg[NN];
__device__ int   g_rowptr[NN + 1];
__device__ int   g_cursor[NN];
__device__ int   g_srcA[EE];
__device__ int   g_eidA[EE];
__device__ int   g_bsum[NBLK];
__device__ int   g_boff[NBLK];
__device__ float g_counts[Bb];
__device__ float g_pooled[Bb * Hh];
__device__ float g_vn[Bb * Hh];
__device__ __nv_bfloat16 g_whi[15 * Hh * Hh];  // [mat][n][k] transposed split
__device__ __nv_bfloat16 g_wlo[15 * Hh * Hh];

// ======================= preprocessing =======================
__global__ void k_wsplit(const float* __restrict__ nodeW, const float* __restrict__ m1W,
                         const float* __restrict__ m2W) {
    int b = blockIdx.x;
    int mat = b >> 6;
    int idx = ((b & 63) << 8) + threadIdx.x;   // 0..16383 over [n][k]
    const float* Wsrc = (mat < 5) ? (nodeW + (size_t)mat * Hh * Hh)
                      : (mat < 10) ? (m1W + (size_t)(mat - 5) * Hh * Hh)
                      : (m2W + (size_t)(mat - 10) * Hh * Hh);
    int n = idx >> 7, k = idx & 127;
    float w = Wsrc[k * Hh + n];
    __nv_bfloat16 hi = __float2bfloat16(w);
    __nv_bfloat16 lo = __float2bfloat16(w - __bfloat162float(hi));
    g_whi[(size_t)mat * Hh * Hh + idx] = hi;
    g_wlo[(size_t)mat * Hh * Hh + idx] = lo;
}

__global__ void k_vn_init(const float* __restrict__ vninit) {
    g_vn[blockIdx.x * Hh + threadIdx.x] = vninit[threadIdx.x];
}

__global__ void k_counts(const int* __restrict__ batch) {
    int i = blockIdx.x * 256 + threadIdx.x;
    if (i < NN) atomicAdd(&g_counts[batch[i]], 1.0f);
}

__global__ void k_deg(const int* __restrict__ dst) {
    int e = blockIdx.x * 256 + threadIdx.x;
    if (e < EE) atomicAdd(&g_deg[dst[e]], 1);
}

__global__ void k_bsum() {
    __shared__ int s[256];
    int t = threadIdx.x;
    int i = blockIdx.x * 256 + t;
    s[t] = (i < NN) ? g_deg[i] : 0;
    __syncthreads();
    for (int o = 128; o > 0; o >>= 1) {
        if (t < o) s[t] += s[t + o];
        __syncthreads();
    }
    if (t == 0) g_bsum[blockIdx.x] = s[0];
}

__global__ void k_bscan() {
    __shared__ int s[256];
    int t = threadIdx.x;
    int v = (t < NBLK) ? g_bsum[t] : 0;
    s[t] = v;
    __syncthreads();
    for (int o = 1; o < 256; o <<= 1) {
        int u = (t >= o) ? s[t - o] : 0;
        __syncthreads();
        s[t] += u;
        __syncthreads();
    }
    if (t < NBLK) g_boff[t] = s[t] - v;
    if (t == 255) g_rowptr[NN] = s[255];
}

__global__ void k_bfill() {
    __shared__ int s[256];
    int t = threadIdx.x;
    int i = blockIdx.x * 256 + t;
    int v = (i < NN) ? g_deg[i] : 0;
    s[t] = v;
    __syncthreads();
    for (int o = 1; o < 256; o <<= 1) {
        int u = (t >= o) ? s[t - o] : 0;
        __syncthreads();
        s[t] += u;
        __syncthreads();
    }
    if (i < NN) {
        int pos = g_boff[blockIdx.x] + s[t] - v;
        g_rowptr[i] = pos;
        g_cursor[i] = pos;
    }
}

__global__ void k_fill(const int* __restrict__ src, const int* __restrict__ dst) {
    int e = blockIdx.x * 256 + threadIdx.x;
    if (e >= EE) return;
    int d = dst[e];
    int pos = atomicAdd(&g_cursor[d], 1);
    g_srcA[pos] = src[e];
    g_eidA[pos] = e;
}

__global__ void k_eagg(const float* __restrict__ eattr) {
    int w = (blockIdx.x * 256 + threadIdx.x) >> 5;
    int lane = threadIdx.x & 31;
    if (w >= NN || lane >= EDdim) return;
    int beg = g_rowptr[w], end = g_rowptr[w + 1];
    float s = 0.f;
    for (int e = beg; e < end; e++) {
        int eid = g_eidA[e];
        s += eattr[(size_t)eid * EDdim + lane];
    }
    g_eagg[w * EDdim + lane] = s;
}

// ======================= HMMA bf16-split GEMM (reg-A + ldmatrix-B) =======================
// C[M,128] = A[M,128] @ W[128,128]; D = Ahi@Bhi + Ahi@Blo + Alo@Bhi (fp32 accum).
// EPI 0: +bias +vn[batch]; EPI 1: relu(+bias); EPI 2: relu(+bias) + pooled atomic.

__device__ __forceinline__ void mma16816(float* c, uint32_t a0, uint32_t a1, uint32_t a2,
                                         uint32_t a3, uint32_t b0, uint32_t b1) {
    asm volatile(
        "mma.sync.aligned.m16n8k16.row.col.f32.bf16.bf16.f32 "
        "{%0,%1,%2,%3}, {%4,%5,%6,%7}, {%8,%9}, {%0,%1,%2,%3};"
        : "+f"(c[0]), "+f"(c[1]), "+f"(c[2]), "+f"(c[3])
        : "r"(a0), "r"(a1), "r"(a2), "r"(a3), "r"(b0), "r"(b1));
}

#define LDSM4(r0, r1, r2, r3, addr) \
    asm volatile("ldmatrix.sync.aligned.m8n8.x4.shared.b16 {%0,%1,%2,%3}, [%4];" \
                 : "=r"(r0), "=r"(r1), "=r"(r2), "=r"(r3) : "r"(addr))

__device__ __forceinline__ uint32_t smem_to_u32(const void* p) {
    uint32_t a;
    asm("{ .reg .u64 t; cvta.to.shared.u64 t, %1; cvt.u32.u64 %0, t; }" : "=r"(a) : "l"(p));
    return a;
}

// pack float2 (v.x = even k, v.y = odd k) into bf16x2 hi + residual lo words
__device__ __forceinline__ void packsplit(float2 v, uint32_t& h, uint32_t& l) {
    uint32_t hp;
    asm("cvt.rn.bf16x2.f32 %0, %1, %2;" : "=r"(hp) : "f"(v.y), "f"(v.x));
    float h0 = __uint_as_float(hp << 16);
    float h1 = __uint_as_float(hp & 0xffff0000u);
    uint32_t lp;
    asm("cvt.rn.bf16x2.f32 %0, %1, %2;" : "=r"(lp) : "f"(v.y - h1), "f"(v.x - h0));
    h = hp;
    l = lp;
}

template <int EPI>
__launch_bounds__(256, 2)
__global__ void gemm_tc(const float* __restrict__ A, const __nv_bfloat16* __restrict__ Whi,
                        const __nv_bfloat16* __restrict__ Wlo, const float* __restrict__ bias,
                        float* __restrict__ C, const int* __restrict__ batch,
                        const float* __restrict__ vn, float* __restrict__ pooled, int M) {
    extern __shared__ __nv_bfloat16 sm[];
    const int tid = threadIdx.x;
    const int wid = tid >> 5;
    const int lane = tid & 31;
    const int tb = blockIdx.x * 128;

    // ---- stage pre-split W [n][k] into smem (hi plane + lo plane) ----
#pragma unroll
    for (int it = 0; it < 8; it++) {
        int idx = it * 256 + tid;
        int n = idx >> 4;
        int k8 = (idx & 15) << 3;
        uint4 hv = *(const uint4*)(Whi + (size_t)n * Hh + k8);
        uint4 lv = *(const uint4*)(Wlo + (size_t)n * Hh + k8);
        *(uint4*)&sm[n * STRIDE + k8] = hv;
        *(uint4*)&sm[BLO_ELEM + n * STRIDE + k8] = lv;
    }

    // ---- per-thread fragment geometry ----
    const int g = lane >> 2;
    const int tig = lane & 3;
    const int r0 = wid * 16 + g;
    const int r1 = r0 + 8;
    const int gr0 = tb + r0;
    const int gr1 = tb + r1;
    const bool v0 = gr0 < M, v1 = gr1 < M;

    const float* Ar0 = A + (size_t)(v0 ? gr0 : 0) * Hh + 2 * tig;
    const float* Ar1 = A + (size_t)(v1 ? gr1 : 0) * Hh + 2 * tig;

    // ldmatrix per-thread row address component
    const int mq = lane >> 3;           // 0..3 (matrix select)
    const int tr = lane & 7;
    const uint32_t smem_u32 = smem_to_u32(sm);
    const uint32_t brow_off = (uint32_t)((((mq >> 1) * 8 + tr) * STRIDE + (mq & 1) * 8) * 2);

    float c[16][4];
#pragma unroll
    for (int n = 0; n < 16; n++)
#pragma unroll
        for (int j = 0; j < 4; j++) c[n][j] = 0.f;

    // prefetch k=0 A fragments (fp32)
    float2 pa0 = *(const float2*)(Ar0);
    float2 pa1 = *(const float2*)(Ar0 + 8);
    float2 pa2 = *(const float2*)(Ar1);
    float2 pa3 = *(const float2*)(Ar1 + 8);

    __syncthreads();

#pragma unroll 1
    for (int k = 0; k < 8; k++) {
        uint32_t ah0, ah1, ah2, ah3, al0, al1, al2, al3;
        packsplit(pa0, ah0, al0);   // (r0, k0)
        packsplit(pa2, ah1, al1);   // (r1, k0)
        packsplit(pa1, ah2, al2);   // (r0, k0+8)
        packsplit(pa3, ah3, al3);   // (r1, k0+8)
        if (k < 7) {
            int off = (k + 1) << 4;
            pa0 = *(const float2*)(Ar0 + off);
            pa1 = *(const float2*)(Ar0 + off + 8);
            pa2 = *(const float2*)(Ar1 + off);
            pa3 = *(const float2*)(Ar1 + off + 8);
        }
        const uint32_t kb = smem_u32 + brow_off + ((uint32_t)k << 5);  // +k0*2 bytes
#pragma unroll
        for (int n2 = 0; n2 < 8; n2++) {
            uint32_t ha = kb + (uint32_t)(n2 * 16 * STRIDE * 2);
            uint32_t la = ha + BLO_ELEM * 2;
            uint32_t bh0, bh1, bh2, bh3, bl0, bl1, bl2, bl3;
            LDSM4(bh0, bh1, bh2, bh3, ha);
            LDSM4(bl0, bl1, bl2, bl3, la);
            mma16816(c[2 * n2], ah0, ah1, ah2, ah3, bh0, bh1);
            mma16816(c[2 * n2], ah0, ah1, ah2, ah3, bl0, bl1);
            mma16816(c[2 * n2], al0, al1, al2, al3, bh0, bh1);
            mma16816(c[2 * n2 + 1], ah0, ah1, ah2, ah3, bh2, bh3);
            mma16816(c[2 * n2 + 1], ah0, ah1, ah2, ah3, bl2, bl3);
            mma16816(c[2 * n2 + 1], al0, al1, al2, al3, bh2, bh3);
        }
    }

    // ---- epilogue ----
    int gc0 = 0, gc1 = 0;
    if (EPI == 0 || EPI == 2) {
        if (v0) gc0 = batch[gr0];
        if (v1) gc1 = batch[gr1];
    }
#pragma unroll
    for (int n = 0; n < 16; n++) {
        int col = (n << 3) + 2 * tig;
        float2 bv = *(const float2*)(bias + col);
        float o0x = c[n][0] + bv.x, o0y = c[n][1] + bv.y;
        float o1x = c[n][2] + bv.x, o1y = c[n][3] + bv.y;
        if (EPI == 0) {
            if (v0) {
                float2 vv = *(const float2*)(vn + gc0 * Hh + col);
                o0x += vv.x; o0y += vv.y;
            }
            if (v1) {
                float2 vv = *(const float2*)(vn + gc1 * Hh + col);
                o1x += vv.x; o1y += vv.y;
            }
        } else {
            o0x = fmaxf(o0x, 0.f); o0y = fmaxf(o0y, 0.f);
            o1x = fmaxf(o1x, 0.f); o1y = fmaxf(o1y, 0.f);
        }
        if (v0) {
            *(float2*)(C + (size_t)gr0 * Hh + col) = make_float2(o0x, o0y);
            if (EPI == 2) {
                atomicAdd(&pooled[gc0 * Hh + col], o0x);
                atomicAdd(&pooled[gc0 * Hh + col + 1], o0y);
            }
        }
        if (v1) {
            *(float2*)(C + (size_t)gr1 * Hh + col) = make_float2(o1x, o1y);
            if (EPI == 2) {
                atomicAdd(&pooled[gc1 * Hh + col], o1x);
                atomicAdd(&pooled[gc1 * Hh + col + 1], o1y);
            }
        }
    }
}

// ======================= SpMM =======================
__launch_bounds__(256)
__global__ void spmm(const float* __restrict__ h, const float* __restrict__ eW,
                     const float* __restrict__ eb, float* __restrict__ agg) {
    __shared__ float sW[EDdim * Hh];
    for (int i = threadIdx.x; i < EDdim * Hh; i += 256) sW[i] = eW[i];
    __syncthreads();
    int warp = (blockIdx.x * 256 + threadIdx.x) >> 5;
    int lane = threadIdx.x & 31;
    if (warp >= NN) return;
    const int row = warp;
    const int c4 = lane << 2;

    float4 acc = make_float4(0.f, 0.f, 0.f, 0.f);
    const float* ea = g_eagg + row * EDdim;
#pragma unroll
    for (int k = 0; k < EDdim; k++) {
        float v = ea[k];
        float4 w = *(const float4*)&sW[k * Hh + c4];
        acc.x = fmaf(v, w.x, acc.x);
        acc.y = fmaf(v, w.y, acc.y);
        acc.z = fmaf(v, w.z, acc.z);
        acc.w = fmaf(v, w.w, acc.w);
    }
    int beg = g_rowptr[row];
    int end = g_rowptr[row + 1];
    float degf = (float)(end - beg);
    float4 bb = *(const float4*)(eb + c4);
    acc.x = fmaf(degf, bb.x, acc.x);
    acc.y = fmaf(degf, bb.y, acc.y);
    acc.z = fmaf(degf, bb.z, acc.z);
    acc.w = fmaf(degf, bb.w, acc.w);

    int e = beg;
    for (; e + 1 < end; e += 2) {
        int s0 = g_srcA[e];
        int s1 = g_srcA[e + 1];
        float4 h0 = *(const float4*)(h + (size_t)s0 * Hh + c4);
        float4 h1 = *(const float4*)(h + (size_t)s1 * Hh + c4);
        acc.x += h0.x + h1.x;
        acc.y += h0.y + h1.y;
        acc.z += h0.z + h1.z;
        acc.w += h0.w + h1.w;
    }
    if (e < end) {
        int s0 = g_srcA[e];
        float4 h0 = *(const float4*)(h + (size_t)s0 * Hh + c4);
        acc.x += h0.x;
        acc.y += h0.y;
        acc.z += h0.z;
        acc.w += h0.w;
    }
    *(float4*)(agg + (size_t)row * Hh + c4) = acc;
}

// ======================= small dense tails =======================
__global__ void vn_update(const float* __restrict__ w0, const float* __restrict__ b0,
                          const float* __restrict__ w1, const float* __restrict__ b1) {
    __shared__ float p[Hh];
    __shared__ float r0[Hh];
    int g = blockIdx.x, j = threadIdx.x;
    float cnt = fmaxf(g_counts[g], 1.f);
    p[j] = g_pooled[g * Hh + j] / cnt;
    __syncthreads();
    float s = b0[j];
    for (int k = 0; k < Hh; k++) s = fmaf(p[k], w0[k * Hh + j], s);
    r0[j] = fmaxf(s, 0.f);
    __syncthreads();
    float s2 = b1[j];
    for (int k = 0; k < Hh; k++) s2 = fmaf(r0[k], w1[k * Hh + j], s2);
    g_vn[g * Hh + j] += fmaxf(s2, 0.f);
}

__global__ void final_fc(const float* __restrict__ fcW, const float* __restrict__ fcb,
                         float* __restrict__ out) {
    __shared__ float p[Hh];
    int g = blockIdx.x, j = threadIdx.x;
    float cnt = fmaxf(g_counts[g], 1.f);
    p[j] = g_pooled[g * Hh + j] / cnt;
    __syncthreads();
    float s = fcb[j];
    for (int k = 0; k < Hh; k++) s = fmaf(p[k], fcW[k * Hh + j], s);
    out[g * Hh + j] = s;
}

// ======================= launch =======================
extern "C" void kernel_launch(void* const* d_in, const int* in_sizes, int n_in,
                              void* d_out, int out_size) {
    const float* x      = (const float*)d_in[0];
    const float* eattr  = (const float*)d_in[1];
    const float* nodeW  = (const float*)d_in[2];
    const float* nodeB  = (const float*)d_in[3];
    const float* edgeW  = (const float*)d_in[4];
    const float* edgeB  = (const float*)d_in[5];
    const float* m1W    = (const float*)d_in[6];
    const float* m1B    = (const float*)d_in[7];
    const float* m2W    = (const float*)d_in[8];
    const float* m2B    = (const float*)d_in[9];
    const float* vnw0   = (const float*)d_in[10];
    const float* vnb0   = (const float*)d_in[11];
    const float* vnw1   = (const float*)d_in[12];
    const float* vnb1   = (const float*)d_in[13];
    const float* fcW    = (const float*)d_in[14];
    const float* fcB    = (const float*)d_in[15];
    const float* vninit = (const float*)d_in[16];
    const int*   eidx   = (const int*)d_in[17];
    const int*   batch  = (const int*)d_in[18];
    const int* srcp = eidx;
    const int* dstp = eidx + EE;
    float* out = (float*)d_out;

    void *p_deg, *p_counts, *p_pooled, *p_x, *p_h, *p_agg, *p_vn, *p_whi, *p_wlo;
    cudaGetSymbolAddress(&p_deg, g_deg);
    cudaGetSymbolAddress(&p_counts, g_counts);
    cudaGetSymbolAddress(&p_pooled, g_pooled);
    cudaGetSymbolAddress(&p_x, g_x);
    cudaGetSymbolAddress(&p_h, g_h);
    cudaGetSymbolAddress(&p_agg, g_agg);
    cudaGetSymbolAddress(&p_vn, g_vn);
    cudaGetSymbolAddress(&p_whi, g_whi);
    cudaGetSymbolAddress(&p_wlo, g_wlo);

    cudaFuncSetAttribute(gemm_tc<0>, cudaFuncAttributeMaxDynamicSharedMemorySize, GEMM_SMEM);
    cudaFuncSetAttribute(gemm_tc<1>, cudaFuncAttributeMaxDynamicSharedMemorySize, GEMM_SMEM);
    cudaFuncSetAttribute(gemm_tc<2>, cudaFuncAttributeMaxDynamicSharedMemorySize, GEMM_SMEM);

    const __nv_bfloat16* whi = (const __nv_bfloat16*)p_whi;
    const __nv_bfloat16* wlo = (const __nv_bfloat16*)p_wlo;

    // launches 1..5 (memsets count), so first GEMM is #6 for the ncu window
    cudaMemsetAsync(p_deg, 0, sizeof(int) * NN);           // 1
    cudaMemsetAsync(p_counts, 0, sizeof(float) * Bb);      // 2
    k_wsplit<<<960, 256>>>(nodeW, m1W, m2W);               // 3
    k_vn_init<<<Bb, Hh>>>(vninit);                         // 4
    k_counts<<<(NN + 255) / 256, 256>>>(batch);            // 5
    gemm_tc<0><<<GBLK, 256, GEMM_SMEM>>>(x, whi, wlo, nodeB,   // 6  <- profiled
                                         (float*)p_h, batch, (const float*)p_vn, nullptr, NN);

    // CSR build (independent of gemm0)
    k_deg<<<(EE + 255) / 256, 256>>>(dstp);
    k_bsum<<<NBLK, 256>>>();
    k_bscan<<<1, 256>>>();
    k_bfill<<<NBLK, 256>>>();
    k_fill<<<(EE + 255) / 256, 256>>>(srcp, dstp);
    k_eagg<<<(NN + 7) / 8, 256>>>(eattr);

    const int SPB = (NN + 7) / 8;

    for (int l = 0; l < Ll; l++) {
        if (l > 0) {
            gemm_tc<0><<<GBLK, 256, GEMM_SMEM>>>((const float*)p_x, whi + (size_t)l * Hh * Hh,
                                                 wlo + (size_t)l * Hh * Hh, nodeB + l * Hh,
                                                 (float*)p_h, batch, (const float*)p_vn, nullptr, NN);
        }
        spmm<<<SPB, 256>>>((const float*)p_h, edgeW + (size_t)l * EDdim * Hh,
                           edgeB + l * Hh, (float*)p_agg);
        cudaMemsetAsync(p_pooled, 0, sizeof(float) * Bb * Hh);
        gemm_tc<1><<<GBLK, 256, GEMM_SMEM>>>((const float*)p_agg, whi + (size_t)(5 + l) * Hh * Hh,
                                             wlo + (size_t)(5 + l) * Hh * Hh, m1B + l * Hh,
                                             (float*)p_h, nullptr, nullptr, nullptr, NN);
        gemm_tc<2><<<GBLK, 256, GEMM_SMEM>>>((const float*)p_h, whi + (size_t)(10 + l) * Hh * Hh,
                                             wlo + (size_t)(10 + l) * Hh * Hh, m2B + l * Hh,
                                             (float*)p_x, batch, nullptr, (float*)p_pooled, NN);
        if (l < Ll - 1) vn_update<<<Bb, Hh>>>(vnw0, vnb0, vnw1, vnb1);
    }
    final_fc<<<Bb, Hh>>>(fcW, fcB, out);
}